// round 14
// baseline (speedup 1.0000x reference)
#include <cuda_runtime.h>
#include <math.h>

#define N_NODES 100000
#define N_EDGES 1600000
#define HALF_E  (N_EDGES / 2)
#define WJPITCH 29

typedef unsigned long long u64;

__device__ float g_dot[N_EDGES];
__device__ float g_m[N_NODES];
__device__ float g_s[N_NODES];

// ---- packed f32x2 helpers ----
union PU { u64 u; float2 f; };

__device__ __forceinline__ u64 pk(float lo, float hi) {
    PU p; p.f.x = lo; p.f.y = hi; return p.u;
}
__device__ __forceinline__ float2 upk2(u64 x) { PU p; p.u = x; return p.f; }

__device__ __forceinline__ u64 fma2(u64 a, u64 b, u64 c) {
    u64 d; asm("fma.rn.f32x2 %0,%1,%2,%3;" : "=l"(d) : "l"(a), "l"(b), "l"(c)); return d;
}
__device__ __forceinline__ u64 add2(u64 a, u64 b) {
    u64 d; asm("add.rn.f32x2 %0,%1,%2;" : "=l"(d) : "l"(a), "l"(b)); return d;
}
__device__ __forceinline__ u64 mul2(u64 a, u64 b) {
    u64 d; asm("mul.rn.f32x2 %0,%1,%2;" : "=l"(d) : "l"(a), "l"(b)); return d;
}

// one radial-pair's packed weights (lane lo = first MLP, lane hi = second MLP)
struct SWPair {
    u64 W1[3][16];
    u64 b1[16], g1[16], be1[16];
    u64 W2[16][16];
    u64 b2[16], g2[16], be2[16];
    float wqs[8];
};

// one-pass LN with tree reductions + clamped variance, then ReLU
__device__ __forceinline__ void ln_relu_pk(u64* h, const u64* g, const u64* be) {
    u64 a0 = add2(h[0], h[1]),  a1 = add2(h[2], h[3]);
    u64 a2 = add2(h[4], h[5]),  a3 = add2(h[6], h[7]);
    u64 a4 = add2(h[8], h[9]),  a5 = add2(h[10], h[11]);
    u64 a6 = add2(h[12], h[13]), a7 = add2(h[14], h[15]);
    a0 = add2(a0, a1); a2 = add2(a2, a3); a4 = add2(a4, a5); a6 = add2(a6, a7);
    a0 = add2(a0, a2); a4 = add2(a4, a6);
    u64 s = add2(a0, a4);
    u64 q0 = mul2(h[0], h[0]);  q0 = fma2(h[1], h[1], q0);
    u64 q1 = mul2(h[2], h[2]);  q1 = fma2(h[3], h[3], q1);
    u64 q2 = mul2(h[4], h[4]);  q2 = fma2(h[5], h[5], q2);
    u64 q3 = mul2(h[6], h[6]);  q3 = fma2(h[7], h[7], q3);
    u64 q4 = mul2(h[8], h[8]);  q4 = fma2(h[9], h[9], q4);
    u64 q5 = mul2(h[10], h[10]); q5 = fma2(h[11], h[11], q5);
    u64 q6 = mul2(h[12], h[12]); q6 = fma2(h[13], h[13], q6);
    u64 q7 = mul2(h[14], h[14]); q7 = fma2(h[15], h[15], q7);
    q0 = add2(q0, q1); q2 = add2(q2, q3); q4 = add2(q4, q5); q6 = add2(q6, q7);
    q0 = add2(q0, q2); q4 = add2(q4, q6);
    u64 s2 = add2(q0, q4);

    float2 S = upk2(s), Q = upk2(s2);
    float mu0 = S.x * 0.0625f, mu1 = S.y * 0.0625f;
    float var0 = fmaxf(fmaf(-mu0, mu0, Q.x * 0.0625f), 0.f);
    float var1 = fmaxf(fmaf(-mu1, mu1, Q.y * 0.0625f), 0.f);
    float inv0 = rsqrtf(var0 + 1e-5f);
    float inv1 = rsqrtf(var1 + 1e-5f);
    u64 invb = pk(inv0, inv1);
    u64 nmi  = pk(-mu0 * inv0, -mu1 * inv1);
#pragma unroll
    for (int j = 0; j < 16; j++) {
        u64 tj = mul2(invb, g[j]);
        u64 cj = fma2(nmi, g[j], be[j]);
        PU val; val.u = fma2(h[j], tj, cj);
        val.f.x = fmaxf(val.f.x, 0.f);
        val.f.y = fmaxf(val.f.y, 0.f);
        h[j] = val.u;
    }
}

template <int OUT>
__device__ __forceinline__ void radial_pair(const SWPair& sw, const u64* W3, const u64* b3,
                                            u64 va, u64 vb, u64 vc, u64* R) {
    u64 h[16];
#pragma unroll
    for (int j = 0; j < 16; j++) h[j] = sw.b1[j];
#pragma unroll
    for (int j = 0; j < 16; j++) h[j] = fma2(va, sw.W1[0][j], h[j]);
#pragma unroll
    for (int j = 0; j < 16; j++) h[j] = fma2(vb, sw.W1[1][j], h[j]);
#pragma unroll
    for (int j = 0; j < 16; j++) h[j] = fma2(vc, sw.W1[2][j], h[j]);
    ln_relu_pk(h, sw.g1, sw.be1);

    u64 acc[16];
#pragma unroll
    for (int j = 0; j < 16; j++) acc[j] = sw.b2[j];
#pragma unroll
    for (int k = 0; k < 16; k++) {
#pragma unroll
        for (int j = 0; j < 16; j++)
            acc[j] = fma2(h[k], sw.W2[k][j], acc[j]);
    }
    ln_relu_pk(acc, sw.g2, sw.be2);

#pragma unroll
    for (int o = 0; o < OUT; o++) R[o] = b3[o];
#pragma unroll
    for (int k = 0; k < 16; k++) {
#pragma unroll
        for (int o = 0; o < OUT; o++)
            R[o] = fma2(acc[k], W3[k * OUT + o], R[o]);
    }
}

__device__ __forceinline__ void atomicMaxF(float* addr, float val) {
    if (val >= 0.f) atomicMax((int*)addr, __float_as_int(val));
    else            atomicMin((unsigned int*)addr, __float_as_uint(val));
}

// shared per-pair weight loader (pair = 0 or 1; MLPs 2p and 2p+1)
__device__ __forceinline__ void load_pair_weights(
    SWPair& sw, int p, int t,
    const float* rW1, const float* rb1, const float* g1, const float* be1,
    const float* rW2, const float* rb2, const float* g2, const float* be2,
    const float* wq)
{
    for (int i = t; i < 48; i += 128)
        ((u64*)sw.W1)[i] = pk(rW1[(2 * p) * 48 + i], rW1[(2 * p + 1) * 48 + i]);
    for (int i = t; i < 16; i += 128) {
        sw.b1[i]  = pk(rb1[(2 * p) * 16 + i], rb1[(2 * p + 1) * 16 + i]);
        sw.g1[i]  = pk(g1[(2 * p) * 16 + i],  g1[(2 * p + 1) * 16 + i]);
        sw.be1[i] = pk(be1[(2 * p) * 16 + i], be1[(2 * p + 1) * 16 + i]);
        sw.b2[i]  = pk(rb2[(2 * p) * 16 + i], rb2[(2 * p + 1) * 16 + i]);
        sw.g2[i]  = pk(g2[(2 * p) * 16 + i],  g2[(2 * p + 1) * 16 + i]);
        sw.be2[i] = pk(be2[(2 * p) * 16 + i], be2[(2 * p + 1) * 16 + i]);
    }
    for (int i = t; i < 256; i += 128)
        ((u64*)sw.W2)[i] = pk(rW2[(2 * p) * 256 + i], rW2[(2 * p + 1) * 256 + i]);
    for (int i = t; i < 8; i += 128) sw.wqs[i] = wq[i];
}

__global__ void init_kernel() {
    int n = blockIdx.x * blockDim.x + threadIdx.x;
    if (n < N_NODES) {
        g_m[n] = -INFINITY;
        g_s[n] = 0.f;
    }
}

// ===== kernel A: radial pair 0 (l=0) -> partial dot =====
__global__ __launch_bounds__(128, 4) void edgeA_kernel(
    const float* __restrict__ f0, const float* __restrict__ f1,
    const float* __restrict__ dist,
    const int* __restrict__ u, const int* __restrict__ v,
    const float* __restrict__ wq,
    const float* __restrict__ wj00, const float* __restrict__ wj01,
    const float* __restrict__ rW1, const float* __restrict__ rb1,
    const float* __restrict__ g1, const float* __restrict__ be1,
    const float* __restrict__ rW2, const float* __restrict__ rb2,
    const float* __restrict__ g2, const float* __restrict__ be2,
    const float* __restrict__ W3_00, const float* __restrict__ b3_00,
    const float* __restrict__ W3_01, const float* __restrict__ b3_01)
{
    __shared__ SWPair sw;
    __shared__ u64 W3s[16][4];
    __shared__ u64 b3s[4];
    {
        int t = threadIdx.x;
        load_pair_weights(sw, 0, t, rW1, rb1, g1, be1, rW2, rb2, g2, be2, wq);
        for (int i = t; i < 64; i += 128) ((u64*)W3s)[i] = pk(W3_00[i], W3_01[i]);
        for (int i = t; i < 4; i += 128) b3s[i] = pk(b3_00[i], b3_01[i]);
    }
    __syncthreads();

    int e = blockIdx.x * 128 + threadIdx.x;

    int uu = u[e], vv = v[e];
    float v2 = dist[e];
    float wj00e = wj00[e];
    float w0 = wj01[3 * e + 0], w1 = wj01[3 * e + 1], w2 = wj01[3 * e + 2];
    float2 fu = ((const float2*)f0)[uu];
    float2 fv = ((const float2*)f0)[vv];
    float f1v[6];
    {
        const float2* p0 = (const float2*)f1 + 3 * vv;
        float2 x;
        x = p0[0]; f1v[0] = x.x; f1v[1] = x.y;
        x = p0[1]; f1v[2] = x.x; f1v[3] = x.y;
        x = p0[2]; f1v[4] = x.x; f1v[5] = x.y;
    }

    u64 va = pk(fu.x * fv.x, fu.x * fv.x);
    u64 vb = pk(fu.y * fv.y, fu.y * fv.y);
    u64 vc = pk(v2, v2);

    u64 R[4];
    radial_pair<4>(sw, (const u64*)W3s, b3s, va, vb, vc, R);
    float2 r0 = upk2(R[0]), r1 = upk2(R[1]), r2 = upk2(R[2]), r3 = upk2(R[3]);

    float k00 = wj00e * fmaf(r0.x, fv.x, r1.x * fv.y);
    float k01 = wj00e * fmaf(r2.x, fv.x, r3.x * fv.y);
    float t0 = fmaf(w0, f1v[0], fmaf(w1, f1v[1], w2 * f1v[2]));
    float t1 = fmaf(w0, f1v[3], fmaf(w1, f1v[4], w2 * f1v[5]));
    k00 = fmaf(r0.y, t0, fmaf(r1.y, t1, k00));
    k01 = fmaf(r2.y, t0, fmaf(r3.y, t1, k01));

    float q00 = fmaf(sw.wqs[0], fv.x, sw.wqs[1] * fv.y);
    float q01 = fmaf(sw.wqs[2], fv.x, sw.wqs[3] * fv.y);
    g_dot[e] = fmaf(q00, k00, q01 * k01);
}

// ===== kernel B: radial pair 1 (l=1) -> complete dot + atomicMax =====
__global__ __launch_bounds__(128, 4) void edgeB_kernel(
    const float* __restrict__ f0, const float* __restrict__ f1,
    const float* __restrict__ dist,
    const int* __restrict__ u, const int* __restrict__ v,
    const float* __restrict__ wq,
    const float* __restrict__ wj10, const float* __restrict__ wj11,
    const float* __restrict__ rW1, const float* __restrict__ rb1,
    const float* __restrict__ g1, const float* __restrict__ be1,
    const float* __restrict__ rW2, const float* __restrict__ rb2,
    const float* __restrict__ g2, const float* __restrict__ be2,
    const float* __restrict__ W3_10, const float* __restrict__ b3_10,
    const float* __restrict__ W3_11, const float* __restrict__ b3_11)
{
    __shared__ SWPair sw;
    __shared__ u64 W3s[16][12];
    __shared__ u64 b3s[12];
    __shared__ float wj11s[128 * WJPITCH];
    {
        int t = threadIdx.x;
        load_pair_weights(sw, 1, t, rW1, rb1, g1, be1, rW2, rb2, g2, be2, wq);
        for (int i = t; i < 192; i += 128) {
            int k = i / 12, o = i - k * 12;
            float lo = (o < 4) ? W3_10[k * 4 + o] : 0.f;
            ((u64*)W3s)[i] = pk(lo, W3_11[k * 12 + o]);
        }
        for (int i = t; i < 12; i += 128)
            b3s[i] = pk((i < 4) ? b3_10[i] : 0.f, b3_11[i]);
        const float* src = wj11 + (long long)blockIdx.x * 128 * 27;
#pragma unroll
        for (int k = 0; k < 27; k++) {
            int i = t + 128 * k;
            int e = i / 27, j = i - e * 27;
            wj11s[e * WJPITCH + j] = src[i];
        }
    }
    __syncthreads();

    int e = blockIdx.x * 128 + threadIdx.x;

    int uu = u[e], vv = v[e];
    float v2 = dist[e];
    float wj10v[3];
#pragma unroll
    for (int m = 0; m < 3; m++) wj10v[m] = wj10[3 * e + m];
    float2 fu = ((const float2*)f0)[uu];
    float2 fv = ((const float2*)f0)[vv];
    float f1v[6];
    {
        const float2* p0 = (const float2*)f1 + 3 * vv;
        float2 x;
        x = p0[0]; f1v[0] = x.x; f1v[1] = x.y;
        x = p0[1]; f1v[2] = x.x; f1v[3] = x.y;
        x = p0[2]; f1v[4] = x.x; f1v[5] = x.y;
    }

    u64 va = pk(fu.x * fv.x, fu.x * fv.x);
    u64 vb = pk(fu.y * fv.y, fu.y * fv.y);
    u64 vc = pk(v2, v2);

    u64 R[12];
    radial_pair<12>(sw, (const u64*)W3s, b3s, va, vb, vc, R);

    float k1[2][3];
    {
        float2 r0 = upk2(R[0]), r1 = upk2(R[1]), r2 = upk2(R[2]), r3 = upk2(R[3]);
        float d0 = fmaf(r0.x, fv.x, r1.x * fv.y);
        float d1 = fmaf(r2.x, fv.x, r3.x * fv.y);
#pragma unroll
        for (int l = 0; l < 3; l++) {
            k1[0][l] = d0 * wj10v[l];
            k1[1][l] = d1 * wj10v[l];
        }
    }
    const float* wr = &wj11s[threadIdx.x * WJPITCH];
#pragma unroll
    for (int j = 0; j < 3; j++) {
        float r0 = upk2(R[4 * j + 0]).y;
        float r1 = upk2(R[4 * j + 1]).y;
        float r2 = upk2(R[4 * j + 2]).y;
        float r3 = upk2(R[4 * j + 3]).y;
#pragma unroll
        for (int l = 0; l < 3; l++) {
            float w0 = wr[9 * j + 3 * l], w1 = wr[9 * j + 3 * l + 1], w2 = wr[9 * j + 3 * l + 2];
            float s0 = fmaf(w0, f1v[0], fmaf(w1, f1v[1], w2 * f1v[2]));
            float s1 = fmaf(w0, f1v[3], fmaf(w1, f1v[4], w2 * f1v[5]));
            k1[0][l] = fmaf(r0, s0, fmaf(r1, s1, k1[0][l]));
            k1[1][l] = fmaf(r2, s0, fmaf(r3, s1, k1[1][l]));
        }
    }

    float dot = g_dot[e];
#pragma unroll
    for (int o = 0; o < 2; o++) {
#pragma unroll
        for (int m = 0; m < 3; m++) {
            float q1 = fmaf(sw.wqs[4 + o * 2 + 0], f1v[m], sw.wqs[4 + o * 2 + 1] * f1v[3 + m]);
            dot = fmaf(q1, k1[o][m], dot);
        }
    }

    g_dot[e] = dot;
    atomicMaxF(&g_m[vv], dot);
}

__global__ void exp_kernel(const int* __restrict__ v, float* __restrict__ out) {
    int t = blockIdx.x * 256 + threadIdx.x;
    if (t >= HALF_E) return;
    int2 vv = ((const int2*)v)[t];
    float2 d = ((const float2*)g_dot)[t];
    float p0 = __expf(d.x - g_m[vv.x]);
    float p1 = __expf(d.y - g_m[vv.y]);
    float2 po; po.x = p0; po.y = p1;
    ((float2*)out)[t] = po;
    atomicAdd(&g_s[vv.x], p0);
    atomicAdd(&g_s[vv.y], p1);
}

__global__ void norm_kernel(const int* __restrict__ v, float* __restrict__ out) {
    int t = blockIdx.x * 256 + threadIdx.x;
    if (t >= HALF_E) return;
    int2 vv = ((const int2*)v)[t];
    float2 o = ((const float2*)out)[t];
    o.x = o.x / g_s[vv.x];
    o.y = o.y / g_s[vv.y];
    ((float2*)out)[t] = o;
}

extern "C" void kernel_launch(void* const* d_in, const int* in_sizes, int n_in,
                              void* d_out, int out_size) {
    const float* f0    = (const float*)d_in[0];
    const float* f1    = (const float*)d_in[1];
    const float* dist  = (const float*)d_in[2];
    const int*   u     = (const int*)d_in[3];
    const int*   v     = (const int*)d_in[4];
    const float* wq    = (const float*)d_in[5];
    const float* wj00  = (const float*)d_in[6];
    const float* wj01  = (const float*)d_in[7];
    const float* wj10  = (const float*)d_in[8];
    const float* wj11  = (const float*)d_in[9];
    const float* rW1   = (const float*)d_in[10];
    const float* rb1   = (const float*)d_in[11];
    const float* g1    = (const float*)d_in[12];
    const float* be1   = (const float*)d_in[13];
    const float* rW2   = (const float*)d_in[14];
    const float* rb2   = (const float*)d_in[15];
    const float* g2    = (const float*)d_in[16];
    const float* be2   = (const float*)d_in[17];
    const float* W3_00 = (const float*)d_in[18];
    const float* b3_00 = (const float*)d_in[19];
    const float* W3_01 = (const float*)d_in[20];
    const float* b3_01 = (const float*)d_in[21];
    const float* W3_10 = (const float*)d_in[22];
    const float* b3_10 = (const float*)d_in[23];
    const float* W3_11 = (const float*)d_in[24];
    const float* b3_11 = (const float*)d_in[25];
    float* out = (float*)d_out;

    init_kernel<<<(N_NODES + 255) / 256, 256>>>();
    edgeA_kernel<<<N_EDGES / 128, 128>>>(
        f0, f1, dist, u, v, wq, wj00, wj01,
        rW1, rb1, g1, be1, rW2, rb2, g2, be2,
        W3_00, b3_00, W3_01, b3_01);
    edgeB_kernel<<<N_EDGES / 128, 128>>>(
        f0, f1, dist, u, v, wq, wj10, wj11,
        rW1, rb1, g1, be1, rW2, rb2, g2, be2,
        W3_10, b3_10, W3_11, b3_11);
    exp_kernel<<<HALF_E / 256, 256>>>(v, out);
    norm_kernel<<<HALF_E / 256, 256>>>(v, out);
}

// round 15
// speedup vs baseline: 1.0962x; 1.0962x over previous
#include <cuda_runtime.h>
#include <math.h>

#define N_NODES 100000
#define N_EDGES 1600000
#define HALF_E  (N_EDGES / 2)
#define WJPITCH 29

typedef unsigned long long u64;

__device__ float g_dot[N_EDGES];
__device__ float g_m[N_NODES];
__device__ float g_s[N_NODES];

// ---- packed f32x2 helpers ----
union PU { u64 u; float2 f; };

__device__ __forceinline__ u64 pk(float lo, float hi) {
    PU p; p.f.x = lo; p.f.y = hi; return p.u;
}
__device__ __forceinline__ float2 upk2(u64 x) { PU p; p.u = x; return p.f; }

__device__ __forceinline__ u64 fma2(u64 a, u64 b, u64 c) {
    u64 d; asm("fma.rn.f32x2 %0,%1,%2,%3;" : "=l"(d) : "l"(a), "l"(b), "l"(c)); return d;
}
__device__ __forceinline__ u64 add2(u64 a, u64 b) {
    u64 d; asm("add.rn.f32x2 %0,%1,%2;" : "=l"(d) : "l"(a), "l"(b)); return d;
}
__device__ __forceinline__ u64 mul2(u64 a, u64 b) {
    u64 d; asm("mul.rn.f32x2 %0,%1,%2;" : "=l"(d) : "l"(a), "l"(b)); return d;
}

// weights packed across MLP PAIRS: lane lo = MLP 2p, lane hi = MLP 2p+1
struct __align__(16) SWQ {
    u64 W1[2][3][16];
    u64 b1[2][16], g1[2][16], be1[2][16];
    u64 W2[2][16][16];
    u64 b2[2][16], g2[2][16], be2[2][16];
    u64 W3p0[16][4];    // (W3_00, W3_01)
    u64 b3p0[4];
    u64 W3p1[16][12];   // o<4: (W3_10, W3_11); o>=4: (0, W3_11)
    u64 b3p1[12];
    float wqs[8];
};

// one-pass LN with tree reductions + clamped variance; wide (LDS.128) g/be loads
__device__ __forceinline__ void ln_relu_pk(u64* h, const u64* g, const u64* be) {
    u64 a0 = add2(h[0], h[1]),  a1 = add2(h[2], h[3]);
    u64 a2 = add2(h[4], h[5]),  a3 = add2(h[6], h[7]);
    u64 a4 = add2(h[8], h[9]),  a5 = add2(h[10], h[11]);
    u64 a6 = add2(h[12], h[13]), a7 = add2(h[14], h[15]);
    a0 = add2(a0, a1); a2 = add2(a2, a3); a4 = add2(a4, a5); a6 = add2(a6, a7);
    a0 = add2(a0, a2); a4 = add2(a4, a6);
    u64 s = add2(a0, a4);
    u64 q0 = mul2(h[0], h[0]);  q0 = fma2(h[1], h[1], q0);
    u64 q1 = mul2(h[2], h[2]);  q1 = fma2(h[3], h[3], q1);
    u64 q2 = mul2(h[4], h[4]);  q2 = fma2(h[5], h[5], q2);
    u64 q3 = mul2(h[6], h[6]);  q3 = fma2(h[7], h[7], q3);
    u64 q4 = mul2(h[8], h[8]);  q4 = fma2(h[9], h[9], q4);
    u64 q5 = mul2(h[10], h[10]); q5 = fma2(h[11], h[11], q5);
    u64 q6 = mul2(h[12], h[12]); q6 = fma2(h[13], h[13], q6);
    u64 q7 = mul2(h[14], h[14]); q7 = fma2(h[15], h[15], q7);
    q0 = add2(q0, q1); q2 = add2(q2, q3); q4 = add2(q4, q5); q6 = add2(q6, q7);
    q0 = add2(q0, q2); q4 = add2(q4, q6);
    u64 s2 = add2(q0, q4);

    float2 S = upk2(s), Q = upk2(s2);
    float mu0 = S.x * 0.0625f, mu1 = S.y * 0.0625f;
    float var0 = fmaxf(fmaf(-mu0, mu0, Q.x * 0.0625f), 0.f);
    float var1 = fmaxf(fmaf(-mu1, mu1, Q.y * 0.0625f), 0.f);
    float inv0 = rsqrtf(var0 + 1e-5f);
    float inv1 = rsqrtf(var1 + 1e-5f);
    u64 invb = pk(inv0, inv1);
    u64 nmi  = pk(-mu0 * inv0, -mu1 * inv1);
#pragma unroll
    for (int j = 0; j < 16; j += 2) {
        ulonglong2 gg = *(const ulonglong2*)&g[j];     // LDS.128
        ulonglong2 bb = *(const ulonglong2*)&be[j];    // LDS.128
        u64 t0 = mul2(invb, gg.x);
        u64 t1 = mul2(invb, gg.y);
        u64 c0 = fma2(nmi, gg.x, bb.x);
        u64 c1 = fma2(nmi, gg.y, bb.y);
        PU v0c; v0c.u = fma2(h[j],     t0, c0);
        PU v1c; v1c.u = fma2(h[j + 1], t1, c1);
        v0c.f.x = fmaxf(v0c.f.x, 0.f); v0c.f.y = fmaxf(v0c.f.y, 0.f);
        v1c.f.x = fmaxf(v1c.f.x, 0.f); v1c.f.y = fmaxf(v1c.f.y, 0.f);
        h[j] = v0c.u; h[j + 1] = v1c.u;
    }
}

// one packed radial covering MLP pair p; all weight reads via explicit LDS.128
template <int OUT>
__device__ __forceinline__ void radial_pair(const SWQ& sw, int p, const u64* W3, const u64* b3,
                                            u64 va, u64 vb, u64 vc, u64* R) {
    u64 h[16];
#pragma unroll
    for (int j = 0; j < 16; j += 2) {
        ulonglong2 b = *(const ulonglong2*)&sw.b1[p][j];
        ulonglong2 w0 = *(const ulonglong2*)&sw.W1[p][0][j];
        ulonglong2 w1 = *(const ulonglong2*)&sw.W1[p][1][j];
        ulonglong2 w2 = *(const ulonglong2*)&sw.W1[p][2][j];
        h[j]     = fma2(vc, w2.x, fma2(vb, w1.x, fma2(va, w0.x, b.x)));
        h[j + 1] = fma2(vc, w2.y, fma2(vb, w1.y, fma2(va, w0.y, b.y)));
    }
    ln_relu_pk(h, sw.g1[p], sw.be1[p]);

    u64 acc[16];
#pragma unroll
    for (int j = 0; j < 16; j += 2) {
        ulonglong2 b = *(const ulonglong2*)&sw.b2[p][j];
        acc[j] = b.x; acc[j + 1] = b.y;
    }
#pragma unroll
    for (int k = 0; k < 16; k++) {
#pragma unroll
        for (int j = 0; j < 16; j += 2) {
            ulonglong2 w = *(const ulonglong2*)&sw.W2[p][k][j];   // LDS.128
            acc[j]     = fma2(h[k], w.x, acc[j]);
            acc[j + 1] = fma2(h[k], w.y, acc[j + 1]);
        }
    }
    ln_relu_pk(acc, sw.g2[p], sw.be2[p]);

#pragma unroll
    for (int o = 0; o < OUT; o += 2) {
        ulonglong2 b = *(const ulonglong2*)&b3[o];
        R[o] = b.x; R[o + 1] = b.y;
    }
#pragma unroll
    for (int k = 0; k < 16; k++) {
#pragma unroll
        for (int o = 0; o < OUT; o += 2) {
            ulonglong2 w = *(const ulonglong2*)&W3[k * OUT + o];  // LDS.128
            R[o]     = fma2(acc[k], w.x, R[o]);
            R[o + 1] = fma2(acc[k], w.y, R[o + 1]);
        }
    }
}

__device__ __forceinline__ void atomicMaxF(float* addr, float val) {
    if (val >= 0.f) atomicMax((int*)addr, __float_as_int(val));
    else            atomicMin((unsigned int*)addr, __float_as_uint(val));
}

__global__ void init_kernel() {
    int n = blockIdx.x * blockDim.x + threadIdx.x;
    if (n < N_NODES) {
        g_m[n] = -INFINITY;
        g_s[n] = 0.f;
    }
}

__global__ __launch_bounds__(128, 4) void edge_kernel(
    const float* __restrict__ f0, const float* __restrict__ f1,
    const float* __restrict__ dist,
    const int* __restrict__ u, const int* __restrict__ v,
    const float* __restrict__ wq,
    const float* __restrict__ wj00, const float* __restrict__ wj01,
    const float* __restrict__ wj10, const float* __restrict__ wj11,
    const float* __restrict__ rW1, const float* __restrict__ rb1,
    const float* __restrict__ g1, const float* __restrict__ be1,
    const float* __restrict__ rW2, const float* __restrict__ rb2,
    const float* __restrict__ g2, const float* __restrict__ be2,
    const float* __restrict__ W3_00, const float* __restrict__ b3_00,
    const float* __restrict__ W3_01, const float* __restrict__ b3_01,
    const float* __restrict__ W3_10, const float* __restrict__ b3_10,
    const float* __restrict__ W3_11, const float* __restrict__ b3_11)
{
    __shared__ SWQ sw;
    __shared__ float wj11s[128 * WJPITCH];
    {
        int t = threadIdx.x;
        for (int i = t; i < 96; i += 128) {
            int p = i / 48, r = i - p * 48;
            ((u64*)sw.W1)[i] = pk(rW1[(2 * p) * 48 + r], rW1[(2 * p + 1) * 48 + r]);
        }
        for (int i = t; i < 32; i += 128) {
            int p = i / 16, j = i - p * 16;
            ((u64*)sw.b1)[i]  = pk(rb1[(2 * p) * 16 + j], rb1[(2 * p + 1) * 16 + j]);
            ((u64*)sw.g1)[i]  = pk(g1[(2 * p) * 16 + j],  g1[(2 * p + 1) * 16 + j]);
            ((u64*)sw.be1)[i] = pk(be1[(2 * p) * 16 + j], be1[(2 * p + 1) * 16 + j]);
            ((u64*)sw.b2)[i]  = pk(rb2[(2 * p) * 16 + j], rb2[(2 * p + 1) * 16 + j]);
            ((u64*)sw.g2)[i]  = pk(g2[(2 * p) * 16 + j],  g2[(2 * p + 1) * 16 + j]);
            ((u64*)sw.be2)[i] = pk(be2[(2 * p) * 16 + j], be2[(2 * p + 1) * 16 + j]);
        }
        for (int i = t; i < 512; i += 128) {
            int p = i / 256, r = i - p * 256;
            ((u64*)sw.W2)[i] = pk(rW2[(2 * p) * 256 + r], rW2[(2 * p + 1) * 256 + r]);
        }
        for (int i = t; i < 64; i += 128)
            ((u64*)sw.W3p0)[i] = pk(W3_00[i], W3_01[i]);
        for (int i = t; i < 4; i += 128)
            sw.b3p0[i] = pk(b3_00[i], b3_01[i]);
        for (int i = t; i < 192; i += 128) {
            int k = i / 12, o = i - k * 12;
            float lo = (o < 4) ? W3_10[k * 4 + o] : 0.f;
            ((u64*)sw.W3p1)[i] = pk(lo, W3_11[k * 12 + o]);
        }
        for (int i = t; i < 12; i += 128)
            sw.b3p1[i] = pk((i < 4) ? b3_10[i] : 0.f, b3_11[i]);
        for (int i = t; i < 8; i += 128) sw.wqs[i] = wq[i];

        const float* src = wj11 + (long long)blockIdx.x * 128 * 27;
#pragma unroll
        for (int k = 0; k < 27; k++) {
            int i = t + 128 * k;
            int e = i / 27, j = i - e * 27;
            wj11s[e * WJPITCH + j] = src[i];
        }
    }
    __syncthreads();

    int e = blockIdx.x * 128 + threadIdx.x;

    // hoisted per-edge loads
    int uu = u[e], vv = v[e];
    float v2 = dist[e];
    float wj00e = wj00[e];
    float wj01v[3], wj10v[3];
#pragma unroll
    for (int m = 0; m < 3; m++) { wj01v[m] = wj01[3 * e + m]; wj10v[m] = wj10[3 * e + m]; }
    float2 fu = ((const float2*)f0)[uu];
    float2 fv = ((const float2*)f0)[vv];
    float f1v[6];
    {
        const float2* p0 = (const float2*)f1 + 3 * vv;
        float2 x;
        x = p0[0]; f1v[0] = x.x; f1v[1] = x.y;
        x = p0[1]; f1v[2] = x.x; f1v[3] = x.y;
        x = p0[2]; f1v[4] = x.x; f1v[5] = x.y;
    }

    float v0 = fu.x * fv.x;
    float v1 = fu.y * fv.y;
    u64 va = pk(v0, v0), vb = pk(v1, v1), vc = pk(v2, v2);

    float k00, k01;
    float k1[2][3];

    // ==== pair 0: MLP0 (l=0,k=0) lo, MLP1 (l=0,k=1) hi ====
    {
        u64 R[4];
        radial_pair<4>(sw, 0, (const u64*)sw.W3p0, sw.b3p0, va, vb, vc, R);
        float2 r0 = upk2(R[0]), r1 = upk2(R[1]), r2 = upk2(R[2]), r3 = upk2(R[3]);
        k00 = wj00e * fmaf(r0.x, fv.x, r1.x * fv.y);
        k01 = wj00e * fmaf(r2.x, fv.x, r3.x * fv.y);
        float t0 = fmaf(wj01v[0], f1v[0], fmaf(wj01v[1], f1v[1], wj01v[2] * f1v[2]));
        float t1 = fmaf(wj01v[0], f1v[3], fmaf(wj01v[1], f1v[4], wj01v[2] * f1v[5]));
        k00 = fmaf(r0.y, t0, fmaf(r1.y, t1, k00));
        k01 = fmaf(r2.y, t0, fmaf(r3.y, t1, k01));
    }

    // ==== pair 1: MLP2 (l=1,k=0) lo, MLP3 (l=1,k=1) hi ====
    {
        u64 R[12];
        radial_pair<12>(sw, 1, (const u64*)sw.W3p1, sw.b3p1, va, vb, vc, R);
        {
            float2 r0 = upk2(R[0]), r1 = upk2(R[1]), r2 = upk2(R[2]), r3 = upk2(R[3]);
            float d0 = fmaf(r0.x, fv.x, r1.x * fv.y);
            float d1 = fmaf(r2.x, fv.x, r3.x * fv.y);
#pragma unroll
            for (int l = 0; l < 3; l++) {
                k1[0][l] = d0 * wj10v[l];
                k1[1][l] = d1 * wj10v[l];
            }
        }
        const float* wr = &wj11s[threadIdx.x * WJPITCH];
#pragma unroll
        for (int j = 0; j < 3; j++) {
            float r0 = upk2(R[4 * j + 0]).y;
            float r1 = upk2(R[4 * j + 1]).y;
            float r2 = upk2(R[4 * j + 2]).y;
            float r3 = upk2(R[4 * j + 3]).y;
#pragma unroll
            for (int l = 0; l < 3; l++) {
                float w0 = wr[9 * j + 3 * l], w1 = wr[9 * j + 3 * l + 1], w2 = wr[9 * j + 3 * l + 2];
                float s0 = fmaf(w0, f1v[0], fmaf(w1, f1v[1], w2 * f1v[2]));
                float s1 = fmaf(w0, f1v[3], fmaf(w1, f1v[4], w2 * f1v[5]));
                k1[0][l] = fmaf(r0, s0, fmaf(r1, s1, k1[0][l]));
                k1[1][l] = fmaf(r2, s0, fmaf(r3, s1, k1[1][l]));
            }
        }
    }

    // ---- q·k dot, store, atomicMax ----
    float dot = 0.f;
#pragma unroll
    for (int o = 0; o < 2; o++) {
        float q0 = fmaf(sw.wqs[o * 2 + 0], fv.x, sw.wqs[o * 2 + 1] * fv.y);
        dot = fmaf(q0, (o == 0 ? k00 : k01), dot);
#pragma unroll
        for (int m = 0; m < 3; m++) {
            float q1 = fmaf(sw.wqs[4 + o * 2 + 0], f1v[m], sw.wqs[4 + o * 2 + 1] * f1v[3 + m]);
            dot = fmaf(q1, k1[o][m], dot);
        }
    }

    g_dot[e] = dot;
    atomicMaxF(&g_m[vv], dot);
}

__global__ void exp_kernel(const int* __restrict__ v, float* __restrict__ out) {
    int t = blockIdx.x * 256 + threadIdx.x;
    if (t >= HALF_E) return;
    int2 vv = ((const int2*)v)[t];
    float2 d = ((const float2*)g_dot)[t];
    float p0 = __expf(d.x - g_m[vv.x]);
    float p1 = __expf(d.y - g_m[vv.y]);
    float2 po; po.x = p0; po.y = p1;
    ((float2*)out)[t] = po;
    atomicAdd(&g_s[vv.x], p0);
    atomicAdd(&g_s[vv.y], p1);
}

__global__ void norm_kernel(const int* __restrict__ v, float* __restrict__ out) {
    int t = blockIdx.x * 256 + threadIdx.x;
    if (t >= HALF_E) return;
    int2 vv = ((const int2*)v)[t];
    float2 o = ((const float2*)out)[t];
    o.x = o.x / g_s[vv.x];
    o.y = o.y / g_s[vv.y];
    ((float2*)out)[t] = o;
}

extern "C" void kernel_launch(void* const* d_in, const int* in_sizes, int n_in,
                              void* d_out, int out_size) {
    const float* f0    = (const float*)d_in[0];
    const float* f1    = (const float*)d_in[1];
    const float* dist  = (const float*)d_in[2];
    const int*   u     = (const int*)d_in[3];
    const int*   v     = (const int*)d_in[4];
    const float* wq    = (const float*)d_in[5];
    const float* wj00  = (const float*)d_in[6];
    const float* wj01  = (const float*)d_in[7];
    const float* wj10  = (const float*)d_in[8];
    const float* wj11  = (const float*)d_in[9];
    const float* rW1   = (const float*)d_in[10];
    const float* rb1   = (const float*)d_in[11];
    const float* g1    = (const float*)d_in[12];
    const float* be1   = (const float*)d_in[13];
    const float* rW2   = (const float*)d_in[14];
    const float* rb2   = (const float*)d_in[15];
    const float* g2    = (const float*)d_in[16];
    const float* be2   = (const float*)d_in[17];
    const float* W3_00 = (const float*)d_in[18];
    const float* b3_00 = (const float*)d_in[19];
    const float* W3_01 = (const float*)d_in[20];
    const float* b3_01 = (const float*)d_in[21];
    const float* W3_10 = (const float*)d_in[22];
    const float* b3_10 = (const float*)d_in[23];
    const float* W3_11 = (const float*)d_in[24];
    const float* b3_11 = (const float*)d_in[25];
    float* out = (float*)d_out;

    init_kernel<<<(N_NODES + 255) / 256, 256>>>();
    edge_kernel<<<N_EDGES / 128, 128>>>(
        f0, f1, dist, u, v, wq, wj00, wj01, wj10, wj11,
        rW1, rb1, g1, be1, rW2, rb2, g2, be2,
        W3_00, b3_00, W3_01, b3_01, W3_10, b3_10, W3_11, b3_11);
    exp_kernel<<<HALF_E / 256, 256>>>(v, out);
    norm_kernel<<<HALF_E / 256, 256>>>(v, out);
}